// round 1
// baseline (speedup 1.0000x reference)
#include <cuda_runtime.h>

#define NB   8
#define NC   6
#define HH   512
#define WW   512
#define HW   (HH * WW)           // 262144
#define NPIX (NB * HW)           // 2097152

#define TILE 32
#define HALO 5
#define TIN  (TILE + 2 * HALO)   // 42

// Persistent accumulators. Statically zero-initialized; finalize_kernel resets
// them at the end of every launch so each graph replay starts from zero.
__device__ unsigned int g_count = 0u;
__device__ double       g_loss  = 0.0;
__device__ __align__(16) unsigned char g_edge[NPIX];

// ---------------------------------------------------------------------------
// Kernel 1: edge mask via exact integer 11x11 box sum (separable in smem).
// edge(p) != 0  <=>  121 * t(p) != boxsum11x11(t)(p)   (zero padding).
// ---------------------------------------------------------------------------
__global__ void edge_kernel(const int* __restrict__ target) {
    __shared__ int tile[TIN][TIN];
    __shared__ int hsum[TIN][TILE];

    const int bx = blockIdx.x, by = blockIdx.y, b = blockIdx.z;
    const int tx = threadIdx.x, ty = threadIdx.y;
    const int tid = ty * TILE + tx;
    const int* tb = target + b * HW;

    // Load 42x42 tile (zero padded outside the image)
    for (int i = tid; i < TIN * TIN; i += TILE * TILE) {
        const int r = i / TIN, c = i - r * TIN;
        const int gy = by * TILE + r - HALO;
        const int gx = bx * TILE + c - HALO;
        int v = 0;
        if (gy >= 0 && gy < HH && gx >= 0 && gx < WW) v = tb[gy * WW + gx];
        tile[r][c] = v;
    }
    __syncthreads();

    // Horizontal 11-tap sums: 42 rows x 32 output cols
    for (int i = tid; i < TIN * TILE; i += TILE * TILE) {
        const int r = i / TILE, c = i - r * TILE;
        int s = 0;
#pragma unroll
        for (int d = 0; d < 11; d++) s += tile[r][c + d];
        hsum[r][c] = s;
    }
    __syncthreads();

    // Vertical 11-tap sums + compare
    int vs = 0;
#pragma unroll
    for (int d = 0; d < 11; d++) vs += hsum[ty + d][tx];
    const int tcen = tile[ty + HALO][tx + HALO];
    const int e = (121 * tcen != vs) ? 1 : 0;

    const int gy = by * TILE + ty, gx = bx * TILE + tx;
    g_edge[b * HW + gy * WW + gx] = (unsigned char)e;

    // Block reduce edge count -> global atomic
    int c = e;
#pragma unroll
    for (int off = 16; off; off >>= 1) c += __shfl_down_sync(0xffffffffu, c, off);
    __shared__ int wsum[32];
    if ((tid & 31) == 0) wsum[tid >> 5] = c;
    __syncthreads();
    if (tid < 32) {
        int v = wsum[tid];
#pragma unroll
        for (int off = 16; off; off >>= 1) v += __shfl_down_sync(0xffffffffu, v, off);
        if (tid == 0) atomicAdd(&g_count, (unsigned int)v);
    }
}

// ---------------------------------------------------------------------------
// Kernel 2: fused log-softmax + smoothed-mask loss, 4 pixels/thread (float4).
// ---------------------------------------------------------------------------
__device__ __forceinline__ float fcomp(const float4& f, int j) {
    return j == 0 ? f.x : j == 1 ? f.y : j == 2 ? f.z : f.w;
}
__device__ __forceinline__ int icomp(const int4& f, int j) {
    return j == 0 ? f.x : j == 1 ? f.y : j == 2 ? f.z : f.w;
}
__device__ __forceinline__ int ucomp(const uchar4& f, int j) {
    return j == 0 ? (int)f.x : j == 1 ? (int)f.y : j == 2 ? (int)f.z : (int)f.w;
}

__global__ void loss_kernel(const float* __restrict__ x,
                            const int* __restrict__ target) {
    const int t4 = blockIdx.x * blockDim.x + threadIdx.x;  // 0 .. NPIX/4-1
    const int p0 = t4 * 4;
    const int b  = p0 >> 18;         // / HW
    const int hw = p0 & (HW - 1);

    const float4* xb = reinterpret_cast<const float4*>(
        x + (size_t)b * NC * HW + hw);
    float4 v[NC];
#pragma unroll
    for (int c = 0; c < NC; c++) v[c] = xb[c * (HW / 4)];

    const int4   lab = *reinterpret_cast<const int4*>(target + p0);
    const uchar4 ev  = *reinterpret_cast<const uchar4*>(g_edge + p0);

    const float s  = fminf(__uint2float_rn(g_count) * (1.0f / (float)NPIX), 0.2f);
    const float cl = 1.0f - 2.0f * s + s * (1.0f / 6.0f);

    float acc = 0.0f;
#pragma unroll
    for (int j = 0; j < 4; j++) {
        const float a0 = fcomp(v[0], j), a1 = fcomp(v[1], j), a2 = fcomp(v[2], j);
        const float a3 = fcomp(v[3], j), a4 = fcomp(v[4], j), a5 = fcomp(v[5], j);
        float m = fmaxf(fmaxf(fmaxf(a0, a1), fmaxf(a2, a3)), fmaxf(a4, a5));
        float es = expf(a0 - m) + expf(a1 - m) + expf(a2 - m) +
                   expf(a3 - m) + expf(a4 - m) + expf(a5 - m);
        const float lse = m + logf(es);

        const int l = icomp(lab, j);
        const float xl = l == 0 ? a0 : l == 1 ? a1 : l == 2 ? a2
                       : l == 3 ? a3 : l == 4 ? a4 : a5;
        const float lp = xl - lse;
        const float S  = (a0 + a1 + a2 + a3 + a4 + a5) - 6.0f * lse;

        acc += ucomp(ev, j) ? (s * S + cl * lp) : lp;
    }

    // Warp + block reduce, then one double atomic per block
#pragma unroll
    for (int off = 16; off; off >>= 1)
        acc += __shfl_down_sync(0xffffffffu, acc, off);
    __shared__ float wsum[8];
    const int lane = threadIdx.x & 31, w = threadIdx.x >> 5;
    if (lane == 0) wsum[w] = acc;
    __syncthreads();
    if (threadIdx.x < 8) {
        float vs = wsum[threadIdx.x];
#pragma unroll
        for (int off = 4; off; off >>= 1)
            vs += __shfl_down_sync(0x000000ffu, vs, off);
        if (threadIdx.x == 0) atomicAdd(&g_loss, (double)vs);
    }
}

// ---------------------------------------------------------------------------
// Kernel 3: write scalar output; reset accumulators for the next replay.
// ---------------------------------------------------------------------------
__global__ void finalize_kernel(float* __restrict__ out) {
    out[0] = (float)(-(g_loss * (1.0 / (double)NPIX)));
    g_loss  = 0.0;
    g_count = 0u;
}

extern "C" void kernel_launch(void* const* d_in, const int* in_sizes, int n_in,
                              void* d_out, int out_size) {
    const float* x      = (const float*)d_in[0];
    const int*   target = (const int*)d_in[1];
    float*       out    = (float*)d_out;

    dim3 eb(TILE, TILE), eg(WW / TILE, HH / TILE, NB);
    edge_kernel<<<eg, eb>>>(target);

    const int threads = 256;
    const int blocks  = (NPIX / 4) / threads;  // 2048
    loss_kernel<<<blocks, threads>>>(x, target);

    finalize_kernel<<<1, 1>>>(out);
}

// round 2
// speedup vs baseline: 1.2269x; 1.2269x over previous
#include <cuda_runtime.h>

#define NB   8
#define NC   6
#define HH   512
#define WW   512
#define HW   (HH * WW)           // 262144
#define NPIX (NB * HW)           // 2097152

#define TW   128                 // tile width (pixels)
#define TH   16                  // tile height
#define HALO 5
#define SMS  152                 // smem row stride (elements); cols stored at +3 so
                                 // center bytes are 4B-aligned for x%4==0

#define NBLOCKS ((WW / TW) * (HH / TH) * NB)   // 4*32*8 = 1024

// Global accumulators: statically zero; last block resets them each launch,
// so every graph replay starts from zero (deterministic).
__device__ double       g_A = 0.0;   // sum lp over all pixels
__device__ double       g_B = 0.0;   // sum S  over edge pixels
__device__ double       g_C = 0.0;   // sum lp over edge pixels
__device__ unsigned int g_count = 0u;
__device__ unsigned int g_done  = 0u;

__global__ void __launch_bounds__(256)
fused_kernel(const float* __restrict__ x,
             const int*   __restrict__ target,
             float*       __restrict__ out) {
    __shared__ unsigned char  t_s[(TH + 10) * SMS];   // 26*152   = 3952 B
    __shared__ unsigned short csum_s[TH * SMS];       // 16*152*2 = 4864 B
    __shared__ unsigned short box_s[TH * TW];         // 2048*2   = 4096 B
    __shared__ float red[3 * 8];
    __shared__ int   redn[8];
    __shared__ bool  is_last;

    const int tid = threadIdx.x;
    const int x0 = blockIdx.x * TW, y0 = blockIdx.y * TH, b = blockIdx.z;
    const int* tb = target + b * HW;

    // ---- Phase 1: load target halo tile (26 x 138) as bytes, zero padded ----
    for (int i = tid; i < (TH + 10) * (TW + 10); i += 256) {
        const int r = i / (TW + 10);
        const int c = i - r * (TW + 10);
        const int gy = y0 + r - HALO;
        const int gx = x0 + c - HALO;
        int v = 0;
        if (gy >= 0 && gy < HH && gx >= 0 && gx < WW) v = tb[gy * WW + gx];
        t_s[r * SMS + c + 3] = (unsigned char)v;
    }
    __syncthreads();

    // ---- Phase 2: vertical sliding 11-sums per column (138 columns) ----
    if (tid < TW + 10) {
        const int c = tid + 3;
        int s = 0;
#pragma unroll
        for (int i = 0; i < 11; i++) s += t_s[i * SMS + c];
        csum_s[c] = (unsigned short)s;
        for (int r = 1; r < TH; r++) {
            s += (int)t_s[(r + 10) * SMS + c] - (int)t_s[(r - 1) * SMS + c];
            csum_s[r * SMS + c] = (unsigned short)s;
        }
    }
    __syncthreads();

    // ---- Phase 3: horizontal sliding 11-sums of csum -> 11x11 box sums ----
    {
        const int r  = tid >> 4;          // 0..15
        const int xs = (tid & 15) * 8;    // segment start (8 outputs/thread)
        int s = 0;
#pragma unroll
        for (int i = 0; i < 11; i++) s += csum_s[r * SMS + xs + 3 + i];
        box_s[r * TW + xs] = (unsigned short)s;
#pragma unroll
        for (int k = 1; k < 8; k++) {
            s += (int)csum_s[r * SMS + xs + 13 + k]
               - (int)csum_s[r * SMS + xs + 2 + k];
            box_s[r * TW + xs + k] = (unsigned short)s;
        }
    }
    __syncthreads();

    // ---- Phase 4: fused log-softmax loss, 8 pixels/thread (2 float4 chunks) ----
    float accA = 0.0f, accB = 0.0f, accC = 0.0f;
    int   accN = 0;
#pragma unroll
    for (int cki = 0; cki < 2; cki++) {
        const int chunk = tid + cki * 256;     // 0..511
        const int px = chunk * 4;              // pixel index in tile
        const int r  = px >> 7;                // /TW
        const int cx = px & (TW - 1);
        const int gy = y0 + r;
        const float* xb = x + (size_t)b * NC * HW + gy * WW + x0 + cx;

        float4 v[NC];
#pragma unroll
        for (int ch = 0; ch < NC; ch++)
            v[ch] = *reinterpret_cast<const float4*>(xb + (size_t)ch * HW);

        // 4 labels (bytes), 4B-aligned thanks to the +3 column shift
        const unsigned int lab4 =
            *reinterpret_cast<const unsigned int*>(&t_s[(r + 5) * SMS + cx + 8]);
        const unsigned short* bx = &box_s[r * TW + cx];

#pragma unroll
        for (int j = 0; j < 4; j++) {
            const float a0 = (&v[0].x)[j], a1 = (&v[1].x)[j], a2 = (&v[2].x)[j];
            const float a3 = (&v[3].x)[j], a4 = (&v[4].x)[j], a5 = (&v[5].x)[j];
            const float m  = fmaxf(fmaxf(fmaxf(a0, a1), fmaxf(a2, a3)),
                                   fmaxf(a4, a5));
            const float es = expf(a0 - m) + expf(a1 - m) + expf(a2 - m) +
                             expf(a3 - m) + expf(a4 - m) + expf(a5 - m);
            const float lse = m + logf(es);

            const int lab = (lab4 >> (8 * j)) & 0xFF;
            const float xl = lab == 0 ? a0 : lab == 1 ? a1 : lab == 2 ? a2
                           : lab == 3 ? a3 : lab == 4 ? a4 : a5;
            const float lp = xl - lse;
            const float S  = (a0 + a1 + a2 + a3 + a4 + a5) - 6.0f * lse;

            const int e = (121 * lab != (int)bx[j]) ? 1 : 0;
            const float ef = (float)e;
            accA += lp;
            accB += ef * S;
            accC += ef * lp;
            accN += e;
        }
    }

    // ---- Block reduction (3 floats + 1 int), then 4 global atomics ----
#pragma unroll
    for (int off = 16; off; off >>= 1) {
        accA += __shfl_down_sync(0xffffffffu, accA, off);
        accB += __shfl_down_sync(0xffffffffu, accB, off);
        accC += __shfl_down_sync(0xffffffffu, accC, off);
        accN += __shfl_down_sync(0xffffffffu, accN, off);
    }
    const int lane = tid & 31, w = tid >> 5;
    if (lane == 0) { red[w] = accA; red[8 + w] = accB; red[16 + w] = accC; redn[w] = accN; }
    __syncthreads();
    if (tid < 8) {
        float a = red[tid], bb = red[8 + tid], c = red[16 + tid];
        int   n = redn[tid];
#pragma unroll
        for (int off = 4; off; off >>= 1) {
            a  += __shfl_down_sync(0x000000ffu, a, off);
            bb += __shfl_down_sync(0x000000ffu, bb, off);
            c  += __shfl_down_sync(0x000000ffu, c, off);
            n  += __shfl_down_sync(0x000000ffu, n, off);
        }
        if (tid == 0) {
            atomicAdd(&g_A, (double)a);
            atomicAdd(&g_B, (double)bb);
            atomicAdd(&g_C, (double)c);
            atomicAdd(&g_count, (unsigned int)n);
        }
    }

    // ---- Last-block finalize: scalar math, output, reset ----
    if (tid == 0) {
        __threadfence();
        const unsigned int prev = atomicAdd(&g_done, 1u);
        is_last = (prev == (unsigned int)(NBLOCKS - 1));
    }
    __syncthreads();
    if (is_last && tid == 0) {
        const double A = atomicAdd(&g_A, 0.0);
        const double B = atomicAdd(&g_B, 0.0);
        const double C = atomicAdd(&g_C, 0.0);
        const unsigned int cnt = atomicAdd(&g_count, 0u);

        const double s  = fmin((double)cnt / (double)NPIX, 0.2);
        const double cl = 1.0 - 2.0 * s + s / 6.0;
        const double total = A + s * B + (cl - 1.0) * C;
        out[0] = (float)(-(total / (double)NPIX));

        g_A = 0.0; g_B = 0.0; g_C = 0.0;
        g_count = 0u; g_done = 0u;
    }
}

extern "C" void kernel_launch(void* const* d_in, const int* in_sizes, int n_in,
                              void* d_out, int out_size) {
    const float* x      = (const float*)d_in[0];
    const int*   target = (const int*)d_in[1];
    float*       out    = (float*)d_out;

    dim3 grid(WW / TW, HH / TH, NB);   // (4, 32, 8) = 1024 blocks
    fused_kernel<<<grid, 256>>>(x, target, out);
}

// round 3
// speedup vs baseline: 1.2370x; 1.0083x over previous
#include <cuda_runtime.h>

#define NB   8
#define NC   6
#define HH   512
#define WW   512
#define HW   (HH * WW)           // 262144
#define NPIX (NB * HW)           // 2097152

#define TW   128                 // edge tile width
#define TH   16                  // edge tile height
#define SMS  152                 // smem byte-row stride; +3 col shift keeps 4B align

#define LOSS_BLOCKS ((NPIX / 4) / 256)   // 2048

// Global accumulators: statically zero; loss kernel's last block resets them,
// so every graph replay starts from zero (deterministic).
__device__ double       g_A = 0.0;   // sum lp over all pixels
__device__ double       g_B = 0.0;   // sum S  over edge pixels
__device__ double       g_C = 0.0;   // sum lp over edge pixels
__device__ unsigned int g_count = 0u;
__device__ unsigned int g_done  = 0u;
__device__ __align__(16) unsigned char g_pack[NPIX];  // label | (edge << 3)

// ---------------------------------------------------------------------------
// Kernel 1: exact integer 11x11 box sum via sliding windows; emit packed byte
//           pack = label | (edge<<3),  edge <=> 121*label != boxsum.
// ---------------------------------------------------------------------------
__global__ void __launch_bounds__(256)
edge_pack_kernel(const int* __restrict__ target) {
    __shared__ unsigned char  t_s[(TH + 10) * SMS];   // 26*152 = 3952 B
    __shared__ unsigned short csum_s[TH * SMS];       // 16*152*2 = 4864 B

    const int tid = threadIdx.x;
    const int x0 = blockIdx.x * TW, y0 = blockIdx.y * TH, b = blockIdx.z;
    const int* tb = target + b * HW;

    // Phase 1: load 26 x 138 halo tile as bytes (zero padded)
    for (int i = tid; i < (TH + 10) * (TW + 10); i += 256) {
        const int r = i / (TW + 10);
        const int c = i - r * (TW + 10);
        const int gy = y0 + r - 5;
        const int gx = x0 + c - 5;
        int v = 0;
        if (gy >= 0 && gy < HH && gx >= 0 && gx < WW) v = tb[gy * WW + gx];
        t_s[r * SMS + c + 3] = (unsigned char)v;
    }
    __syncthreads();

    // Phase 2: vertical sliding 11-sums per column (138 columns)
    if (tid < TW + 10) {
        const int c = tid + 3;
        int s = 0;
#pragma unroll
        for (int i = 0; i < 11; i++) s += t_s[i * SMS + c];
        csum_s[c] = (unsigned short)s;
#pragma unroll 5
        for (int r = 1; r < TH; r++) {
            s += (int)t_s[(r + 10) * SMS + c] - (int)t_s[(r - 1) * SMS + c];
            csum_s[r * SMS + c] = (unsigned short)s;
        }
    }
    __syncthreads();

    // Phase 3: horizontal sliding 11-sums -> box sums; compare; pack; store.
    // Each thread: 8 consecutive pixels of one row -> one 8-byte store.
    {
        const int r  = tid >> 4;          // 0..15
        const int xs = (tid & 15) * 8;    // 0,8,...,120
        int s = 0;
#pragma unroll
        for (int i = 0; i < 11; i++) s += csum_s[r * SMS + xs + 3 + i];

        const unsigned char* lrow = &t_s[(r + 5) * SMS + xs + 8];
        unsigned long long pk = 0ull;
#pragma unroll
        for (int k = 0; k < 8; k++) {
            if (k) s += (int)csum_s[r * SMS + xs + 13 + k]
                      - (int)csum_s[r * SMS + xs + 2 + k];
            const int lab = lrow[k];
            const unsigned long long e = (121 * lab != s) ? 1ull : 0ull;
            pk |= ((unsigned long long)lab | (e << 3)) << (8 * k);
        }
        *reinterpret_cast<unsigned long long*>(
            &g_pack[b * HW + (y0 + r) * WW + x0 + xs]) = pk;
    }
}

// ---------------------------------------------------------------------------
// Kernel 2: pure-streaming fused log-softmax loss, 4 pixels/thread.
// Accumulates A = sum lp, B = sum_edge S, C = sum_edge lp, N = edge count.
// Last block finalizes: loss = -(A + s*B + (cl-1)*C)/NPIX, s = min(N/NPIX,.2)
// ---------------------------------------------------------------------------
__global__ void __launch_bounds__(256)
loss_kernel(const float* __restrict__ x, float* __restrict__ out) {
    const int t4 = blockIdx.x * blockDim.x + threadIdx.x;  // 0 .. NPIX/4-1
    const int p0 = t4 * 4;
    const int b  = p0 >> 18;         // / HW
    const int hw = p0 & (HW - 1);

    const float4* xb = reinterpret_cast<const float4*>(
        x + (size_t)b * NC * HW + hw);
    float4 v[NC];
#pragma unroll
    for (int c = 0; c < NC; c++) v[c] = xb[c * (HW / 4)];

    const unsigned int pk4 = *reinterpret_cast<const unsigned int*>(g_pack + p0);

    float accA = 0.0f, accB = 0.0f, accC = 0.0f;
    int   accN = 0;
#pragma unroll
    for (int j = 0; j < 4; j++) {
        const float a0 = (&v[0].x)[j], a1 = (&v[1].x)[j], a2 = (&v[2].x)[j];
        const float a3 = (&v[3].x)[j], a4 = (&v[4].x)[j], a5 = (&v[5].x)[j];
        const float m  = fmaxf(fmaxf(fmaxf(a0, a1), fmaxf(a2, a3)),
                               fmaxf(a4, a5));
        const float es = expf(a0 - m) + expf(a1 - m) + expf(a2 - m) +
                         expf(a3 - m) + expf(a4 - m) + expf(a5 - m);
        const float lse = m + logf(es);

        const unsigned int pkj = (pk4 >> (8 * j)) & 0xFFu;
        const int lab = (int)(pkj & 7u);
        const int e   = (int)(pkj >> 3);

        const float xl = lab == 0 ? a0 : lab == 1 ? a1 : lab == 2 ? a2
                       : lab == 3 ? a3 : lab == 4 ? a4 : a5;
        const float lp = xl - lse;
        const float S  = (a0 + a1 + a2 + a3 + a4 + a5) - 6.0f * lse;

        const float ef = (float)e;
        accA += lp;
        accB += ef * S;
        accC += ef * lp;
        accN += e;
    }

    // Block reduction, then 4 global atomics
#pragma unroll
    for (int off = 16; off; off >>= 1) {
        accA += __shfl_down_sync(0xffffffffu, accA, off);
        accB += __shfl_down_sync(0xffffffffu, accB, off);
        accC += __shfl_down_sync(0xffffffffu, accC, off);
        accN += __shfl_down_sync(0xffffffffu, accN, off);
    }
    __shared__ float red[3 * 8];
    __shared__ int   redn[8];
    __shared__ bool  is_last;
    const int tid = threadIdx.x;
    const int lane = tid & 31, w = tid >> 5;
    if (lane == 0) { red[w] = accA; red[8 + w] = accB; red[16 + w] = accC; redn[w] = accN; }
    __syncthreads();
    if (tid < 8) {
        float a = red[tid], bb = red[8 + tid], c = red[16 + tid];
        int   n = redn[tid];
#pragma unroll
        for (int off = 4; off; off >>= 1) {
            a  += __shfl_down_sync(0x000000ffu, a, off);
            bb += __shfl_down_sync(0x000000ffu, bb, off);
            c  += __shfl_down_sync(0x000000ffu, c, off);
            n  += __shfl_down_sync(0x000000ffu, n, off);
        }
        if (tid == 0) {
            atomicAdd(&g_A, (double)a);
            atomicAdd(&g_B, (double)bb);
            atomicAdd(&g_C, (double)c);
            atomicAdd(&g_count, (unsigned int)n);
        }
    }

    // Last-block finalize: scalar math, output, reset
    if (tid == 0) {
        __threadfence();
        const unsigned int prev = atomicAdd(&g_done, 1u);
        is_last = (prev == (unsigned int)(LOSS_BLOCKS - 1));
    }
    __syncthreads();
    if (is_last && tid == 0) {
        const double A = atomicAdd(&g_A, 0.0);
        const double B = atomicAdd(&g_B, 0.0);
        const double C = atomicAdd(&g_C, 0.0);
        const unsigned int cnt = atomicAdd(&g_count, 0u);

        const double s  = fmin((double)cnt / (double)NPIX, 0.2);
        const double cl = 1.0 - 2.0 * s + s / 6.0;
        const double total = A + s * B + (cl - 1.0) * C;
        out[0] = (float)(-(total / (double)NPIX));

        g_A = 0.0; g_B = 0.0; g_C = 0.0;
        g_count = 0u; g_done = 0u;
    }
}

extern "C" void kernel_launch(void* const* d_in, const int* in_sizes, int n_in,
                              void* d_out, int out_size) {
    const float* x      = (const float*)d_in[0];
    const int*   target = (const int*)d_in[1];
    float*       out    = (float*)d_out;

    dim3 eg(WW / TW, HH / TH, NB);   // (4, 32, 8) = 1024 blocks
    edge_pack_kernel<<<eg, 256>>>(target);

    loss_kernel<<<LOSS_BLOCKS, 256>>>(x, out);
}

// round 4
// speedup vs baseline: 1.4549x; 1.1761x over previous
#include <cuda_runtime.h>

#define NB   8
#define NC   6
#define HH   512
#define WW   512
#define HW   (HH * WW)           // 262144
#define NPIX (NB * HW)           // 2097152

#define TW   128                 // edge tile width
#define TH   8                   // edge tile height
#define SMS  152                 // smem byte-row stride (+3 col shift)

#define LOSS_BLOCKS ((NPIX / 4) / 256)   // 2048

// Global accumulators: statically zero; loss kernel's last block resets them,
// so every graph replay starts from zero (deterministic).
__device__ double       g_A = 0.0;   // sum lp over all pixels
__device__ double       g_B = 0.0;   // sum S  over edge pixels
__device__ double       g_C = 0.0;   // sum lp over edge pixels
__device__ unsigned int g_count = 0u;
__device__ unsigned int g_done  = 0u;
__device__ __align__(16) unsigned char g_pack[NPIX];  // label | (edge << 3)

// ---------------------------------------------------------------------------
// Kernel 1: exact integer 11x11 box sum via sliding windows; emit packed byte
//           pack = label | (edge<<3),  edge <=> 121*label != boxsum.
// TH=8 rows/tile -> short serial chains, 2048 blocks of parallelism.
// ---------------------------------------------------------------------------
__global__ void __launch_bounds__(256)
edge_pack_kernel(const int* __restrict__ target) {
    __shared__ unsigned char  t_s[(TH + 10) * SMS];   // 18*152 = 2736 B
    __shared__ unsigned short csum_s[TH * SMS];       // 8*152*2 = 2432 B

    const int tid = threadIdx.x;
    const int x0 = blockIdx.x * TW, y0 = blockIdx.y * TH, b = blockIdx.z;
    const int* tb = target + b * HW;

    // Phase 1: load 18 x 138 halo tile as bytes (zero padded)
    for (int i = tid; i < (TH + 10) * (TW + 10); i += 256) {
        const int r = i / (TW + 10);
        const int c = i - r * (TW + 10);
        const int gy = y0 + r - 5;
        const int gx = x0 + c - 5;
        int v = 0;
        if (gy >= 0 && gy < HH && gx >= 0 && gx < WW) v = tb[gy * WW + gx];
        t_s[r * SMS + c + 3] = (unsigned char)v;
    }
    __syncthreads();

    // Phase 2: vertical sliding 11-sums per column (138 columns, 8 rows)
    if (tid < TW + 10) {
        const int c = tid + 3;
        int s = 0;
#pragma unroll
        for (int i = 0; i < 11; i++) s += t_s[i * SMS + c];
        csum_s[c] = (unsigned short)s;
#pragma unroll
        for (int r = 1; r < TH; r++) {
            s += (int)t_s[(r + 10) * SMS + c] - (int)t_s[(r - 1) * SMS + c];
            csum_s[r * SMS + c] = (unsigned short)s;
        }
    }
    __syncthreads();

    // Phase 3: horizontal sliding 11-sums -> box sums; compare; pack; store.
    // 256 threads, each: 4 consecutive pixels of one row -> one 4-byte store.
    {
        const int r  = tid >> 5;          // 0..7
        const int xs = (tid & 31) * 4;    // 0,4,...,124
        int s = 0;
#pragma unroll
        for (int i = 0; i < 11; i++) s += csum_s[r * SMS + xs + 3 + i];

        const unsigned char* lrow = &t_s[(r + 5) * SMS + xs + 8];
        unsigned int pk = 0u;
#pragma unroll
        for (int k = 0; k < 4; k++) {
            if (k) s += (int)csum_s[r * SMS + xs + 13 + k]
                      - (int)csum_s[r * SMS + xs + 2 + k];
            const int lab = lrow[k];
            const unsigned int e = (121 * lab != s) ? 1u : 0u;
            pk |= ((unsigned int)lab | (e << 3)) << (8 * k);
        }
        *reinterpret_cast<unsigned int*>(
            &g_pack[b * HW + (y0 + r) * WW + x0 + xs]) = pk;
    }
}

// ---------------------------------------------------------------------------
// Kernel 2: pure-streaming fused log-softmax loss, 4 pixels/thread.
// Fast-math transcendentals (MUFU EX2/LG2); no max-subtraction (|x|<~6 so
// exp never overflows and precision is far inside the 1e-3 budget).
// ---------------------------------------------------------------------------
__global__ void __launch_bounds__(256)
loss_kernel(const float* __restrict__ x, float* __restrict__ out) {
    const int t4 = blockIdx.x * blockDim.x + threadIdx.x;  // 0 .. NPIX/4-1
    const int p0 = t4 * 4;
    const int b  = p0 >> 18;         // / HW
    const int hw = p0 & (HW - 1);

    const float4* xb = reinterpret_cast<const float4*>(
        x + (size_t)b * NC * HW + hw);
    float4 v[NC];
#pragma unroll
    for (int c = 0; c < NC; c++) v[c] = xb[c * (HW / 4)];

    const unsigned int pk4 = *reinterpret_cast<const unsigned int*>(g_pack + p0);

    float accA = 0.0f, accB = 0.0f, accC = 0.0f;
    int   accN = 0;
#pragma unroll
    for (int j = 0; j < 4; j++) {
        const float a0 = (&v[0].x)[j], a1 = (&v[1].x)[j], a2 = (&v[2].x)[j];
        const float a3 = (&v[3].x)[j], a4 = (&v[4].x)[j], a5 = (&v[5].x)[j];

        const float es = __expf(a0) + __expf(a1) + __expf(a2) +
                         __expf(a3) + __expf(a4) + __expf(a5);
        const float lse = __logf(es);

        const unsigned int pkj = (pk4 >> (8 * j)) & 0xFFu;
        const int lab = (int)(pkj & 7u);
        const int e   = (int)(pkj >> 3);

        const float xl = lab == 0 ? a0 : lab == 1 ? a1 : lab == 2 ? a2
                       : lab == 3 ? a3 : lab == 4 ? a4 : a5;
        const float lp = xl - lse;
        const float S  = (a0 + a1 + a2 + a3 + a4 + a5) - 6.0f * lse;

        const float ef = (float)e;
        accA += lp;
        accB += ef * S;
        accC += ef * lp;
        accN += e;
    }

    // Block reduction, then 4 global atomics
#pragma unroll
    for (int off = 16; off; off >>= 1) {
        accA += __shfl_down_sync(0xffffffffu, accA, off);
        accB += __shfl_down_sync(0xffffffffu, accB, off);
        accC += __shfl_down_sync(0xffffffffu, accC, off);
        accN += __shfl_down_sync(0xffffffffu, accN, off);
    }
    __shared__ float red[3 * 8];
    __shared__ int   redn[8];
    __shared__ bool  is_last;
    const int tid = threadIdx.x;
    const int lane = tid & 31, w = tid >> 5;
    if (lane == 0) { red[w] = accA; red[8 + w] = accB; red[16 + w] = accC; redn[w] = accN; }
    __syncthreads();
    if (tid < 8) {
        float a = red[tid], bb = red[8 + tid], c = red[16 + tid];
        int   n = redn[tid];
#pragma unroll
        for (int off = 4; off; off >>= 1) {
            a  += __shfl_down_sync(0x000000ffu, a, off);
            bb += __shfl_down_sync(0x000000ffu, bb, off);
            c  += __shfl_down_sync(0x000000ffu, c, off);
            n  += __shfl_down_sync(0x000000ffu, n, off);
        }
        if (tid == 0) {
            atomicAdd(&g_A, (double)a);
            atomicAdd(&g_B, (double)bb);
            atomicAdd(&g_C, (double)c);
            atomicAdd(&g_count, (unsigned int)n);
        }
    }

    // Last-block finalize: scalar math, output, reset
    if (tid == 0) {
        __threadfence();
        const unsigned int prev = atomicAdd(&g_done, 1u);
        is_last = (prev == (unsigned int)(LOSS_BLOCKS - 1));
    }
    __syncthreads();
    if (is_last && tid == 0) {
        const double A = atomicAdd(&g_A, 0.0);
        const double B = atomicAdd(&g_B, 0.0);
        const double C = atomicAdd(&g_C, 0.0);
        const unsigned int cnt = atomicAdd(&g_count, 0u);

        const double s  = fmin((double)cnt / (double)NPIX, 0.2);
        const double cl = 1.0 - 2.0 * s + s / 6.0;
        const double total = A + s * B + (cl - 1.0) * C;
        out[0] = (float)(-(total / (double)NPIX));

        g_A = 0.0; g_B = 0.0; g_C = 0.0;
        g_count = 0u; g_done = 0u;
    }
}

extern "C" void kernel_launch(void* const* d_in, const int* in_sizes, int n_in,
                              void* d_out, int out_size) {
    const float* x      = (const float*)d_in[0];
    const int*   target = (const int*)d_in[1];
    float*       out    = (float*)d_out;

    dim3 eg(WW / TW, HH / TH, NB);   // (4, 64, 8) = 2048 blocks
    edge_pack_kernel<<<eg, 256>>>(target);

    loss_kernel<<<LOSS_BLOCKS, 256>>>(x, out);
}

// round 5
// speedup vs baseline: 1.5798x; 1.0858x over previous
#include <cuda_runtime.h>

#define NB   8
#define NC   6
#define HH   512
#define WW   512
#define HW   (HH * WW)           // 262144
#define NPIX (NB * HW)           // 2097152

#define ETH  16                  // edge strip height (full 512-wide rows)
#define SS   528                 // smem column stride; image col c stored at c+8

#define LOSS_BLOCKS ((NPIX / 8) / 256)   // 1024

// Global accumulators: statically zero; loss kernel's last block resets them,
// so every graph replay starts from zero (deterministic).
__device__ double       g_A = 0.0;   // sum lp over all pixels
__device__ double       g_B = 0.0;   // sum S  over edge pixels
__device__ double       g_C = 0.0;   // sum lp over edge pixels
__device__ unsigned int g_count = 0u;
__device__ unsigned int g_done  = 0u;
__device__ __align__(16) unsigned char g_pack[NPIX];  // label | (edge << 3)

// ---------------------------------------------------------------------------
// Kernel 1: full-width strip, exact integer 11x11 box sum, packed byte out.
// Phase 2 uses all 512 threads (one column each); phase 3 is registerized
// (LDS.128 window loads, sliding sums in registers, one STG.128 per thread).
// ---------------------------------------------------------------------------
__global__ void __launch_bounds__(512)
edge_pack_kernel(const int* __restrict__ target) {
    __shared__ unsigned char  t_s[(ETH + 10) * SS];   // 26*528 = 13728 B
    __shared__ unsigned short csum_s[ETH * SS];       // 16*528*2 = 16896 B

    const int tid = threadIdx.x;
    const int y0  = blockIdx.x * ETH;
    const int b   = blockIdx.y;
    const int* tb = target + b * HW;

    // Zero both arrays (guard columns / out-of-image rows must read as 0)
    {
        uint4* p1 = reinterpret_cast<uint4*>(t_s);      // 13728/16 = 858
        for (int i = tid; i < 858; i += 512) p1[i] = make_uint4(0, 0, 0, 0);
        uint4* p2 = reinterpret_cast<uint4*>(csum_s);   // 16896/16 = 1056
        for (int i = tid; i < 1056; i += 512) p2[i] = make_uint4(0, 0, 0, 0);
    }
    __syncthreads();

    // Phase 1: load rows y0-5 .. y0+20 (clamped) as bytes; col c at pos c+8
#pragma unroll
    for (int r = 0; r < ETH + 10; r++) {
        const int gy = y0 + r - 5;
        if (gy >= 0 && gy < HH)
            t_s[r * SS + tid + 8] = (unsigned char)tb[gy * WW + tid];
    }
    __syncthreads();

    // Phase 2: vertical sliding 11-sums; one column per thread (all 512 busy)
    {
        const int pos = tid + 8;
        int s = 0;
#pragma unroll
        for (int i = 0; i < 11; i++) s += t_s[i * SS + pos];
        csum_s[pos] = (unsigned short)s;
#pragma unroll
        for (int r = 1; r < ETH; r++) {
            s += (int)t_s[(r + 10) * SS + pos] - (int)t_s[(r - 1) * SS + pos];
            csum_s[r * SS + pos] = (unsigned short)s;
        }
    }
    __syncthreads();

    // Phase 3: 16 rows x 32 lanes; each thread 16 consecutive pixels.
    {
        const int r  = tid >> 5;          // 0..15
        const int xs = (tid & 31) * 16;   // 0,16,...,496

        // csum window: storage pos xs..xs+31 (= image cols xs-8..xs+23),
        // covering the needed cols xs-5..xs+20. 16B-aligned.
        unsigned int w[16];
        {
            const uint4* src = reinterpret_cast<const uint4*>(&csum_s[r * SS + xs]);
            uint4 u0 = src[0], u1 = src[1], u2 = src[2], u3 = src[3];
            w[0]=u0.x; w[1]=u0.y; w[2]=u0.z; w[3]=u0.w;
            w[4]=u1.x; w[5]=u1.y; w[6]=u1.z; w[7]=u1.w;
            w[8]=u2.x; w[9]=u2.y; w[10]=u2.z; w[11]=u2.w;
            w[12]=u3.x; w[13]=u3.y; w[14]=u3.z; w[15]=u3.w;
        }
#define CS(L) ((int)((w[(L) >> 1] >> (((L) & 1) * 16)) & 0xFFFFu))

        // 16 labels: byte offset (r+5)*SS + xs + 8 is 8-aligned -> 2x LDS.64
        unsigned int lw[4];
        {
            const uint2* lp0 = reinterpret_cast<const uint2*>(
                &t_s[(r + 5) * SS + xs + 8]);
            uint2 l0 = lp0[0], l1 = lp0[1];
            lw[0] = l0.x; lw[1] = l0.y; lw[2] = l1.x; lw[3] = l1.y;
        }

        // Sliding horizontal 11-sums + compare + pack (all in registers)
        int s = 0;
#pragma unroll
        for (int d = 0; d < 11; d++) s += CS(3 + d);

        unsigned int out[4] = {0u, 0u, 0u, 0u};
#pragma unroll
        for (int k = 0; k < 16; k++) {
            if (k) s += CS(k + 13) - CS(k + 2);
            const int lab = (int)((lw[k >> 2] >> (8 * (k & 3))) & 0xFFu);
            const unsigned int e = (121 * lab != s) ? 1u : 0u;
            out[k >> 2] |= ((unsigned int)lab | (e << 3)) << (8 * (k & 3));
        }
#undef CS
        *reinterpret_cast<uint4*>(&g_pack[b * HW + (y0 + r) * WW + xs]) =
            make_uint4(out[0], out[1], out[2], out[3]);
    }
}

// ---------------------------------------------------------------------------
// Kernel 2: pure-streaming fused log-softmax loss, 8 pixels/thread.
// Fast-math MUFU transcendentals; no max-subtraction (|x| <~ 6, safe).
// ---------------------------------------------------------------------------
__global__ void __launch_bounds__(256)
loss_kernel(const float* __restrict__ x, float* __restrict__ out) {
    const int t  = blockIdx.x * blockDim.x + threadIdx.x;  // 0 .. NPIX/8-1
    const int p0 = t * 8;
    const int b  = p0 >> 18;         // / HW
    const int hw = p0 & (HW - 1);

    const float4* xb = reinterpret_cast<const float4*>(
        x + (size_t)b * NC * HW + hw);

    // Issue all 12 vector loads + pack load up front (MLP ~13)
    float4 v[2][NC];
#pragma unroll
    for (int c = 0; c < NC; c++) {
        v[0][c] = xb[c * (HW / 4)];
        v[1][c] = xb[c * (HW / 4) + 1];
    }
    const uint2 pk8 = *reinterpret_cast<const uint2*>(g_pack + p0);

    float accA = 0.0f, accB = 0.0f, accC = 0.0f;
    int   accN = 0;
#pragma unroll
    for (int g = 0; g < 2; g++) {
        const unsigned int pk4 = g ? pk8.y : pk8.x;
#pragma unroll
        for (int j = 0; j < 4; j++) {
            const float a0 = (&v[g][0].x)[j], a1 = (&v[g][1].x)[j];
            const float a2 = (&v[g][2].x)[j], a3 = (&v[g][3].x)[j];
            const float a4 = (&v[g][4].x)[j], a5 = (&v[g][5].x)[j];

            const float es = __expf(a0) + __expf(a1) + __expf(a2) +
                             __expf(a3) + __expf(a4) + __expf(a5);
            const float lse = __logf(es);

            const unsigned int pkj = (pk4 >> (8 * j)) & 0xFFu;
            const int lab = (int)(pkj & 7u);
            const int e   = (int)(pkj >> 3);

            const float xl = lab == 0 ? a0 : lab == 1 ? a1 : lab == 2 ? a2
                           : lab == 3 ? a3 : lab == 4 ? a4 : a5;
            const float lp = xl - lse;
            const float S  = (a0 + a1 + a2 + a3 + a4 + a5) - 6.0f * lse;

            const float ef = (float)e;
            accA += lp;
            accB += ef * S;
            accC += ef * lp;
            accN += e;
        }
    }

    // Block reduction, then 4 global atomics
#pragma unroll
    for (int off = 16; off; off >>= 1) {
        accA += __shfl_down_sync(0xffffffffu, accA, off);
        accB += __shfl_down_sync(0xffffffffu, accB, off);
        accC += __shfl_down_sync(0xffffffffu, accC, off);
        accN += __shfl_down_sync(0xffffffffu, accN, off);
    }
    __shared__ float red[3 * 8];
    __shared__ int   redn[8];
    __shared__ bool  is_last;
    const int tid = threadIdx.x;
    const int lane = tid & 31, w = tid >> 5;
    if (lane == 0) { red[w] = accA; red[8 + w] = accB; red[16 + w] = accC; redn[w] = accN; }
    __syncthreads();
    if (tid < 8) {
        float a = red[tid], bb = red[8 + tid], c = red[16 + tid];
        int   n = redn[tid];
#pragma unroll
        for (int off = 4; off; off >>= 1) {
            a  += __shfl_down_sync(0x000000ffu, a, off);
            bb += __shfl_down_sync(0x000000ffu, bb, off);
            c  += __shfl_down_sync(0x000000ffu, c, off);
            n  += __shfl_down_sync(0x000000ffu, n, off);
        }
        if (tid == 0) {
            atomicAdd(&g_A, (double)a);
            atomicAdd(&g_B, (double)bb);
            atomicAdd(&g_C, (double)c);
            atomicAdd(&g_count, (unsigned int)n);
        }
    }

    // Last-block finalize: scalar math, output, reset
    if (tid == 0) {
        __threadfence();
        const unsigned int prev = atomicAdd(&g_done, 1u);
        is_last = (prev == (unsigned int)(LOSS_BLOCKS - 1));
    }
    __syncthreads();
    if (is_last && tid == 0) {
        const double A = atomicAdd(&g_A, 0.0);
        const double B = atomicAdd(&g_B, 0.0);
        const double C = atomicAdd(&g_C, 0.0);
        const unsigned int cnt = atomicAdd(&g_count, 0u);

        const double s  = fmin((double)cnt / (double)NPIX, 0.2);
        const double cl = 1.0 - 2.0 * s + s / 6.0;
        const double total = A + s * B + (cl - 1.0) * C;
        out[0] = (float)(-(total / (double)NPIX));

        g_A = 0.0; g_B = 0.0; g_C = 0.0;
        g_count = 0u; g_done = 0u;
    }
}

extern "C" void kernel_launch(void* const* d_in, const int* in_sizes, int n_in,
                              void* d_out, int out_size) {
    const float* x      = (const float*)d_in[0];
    const int*   target = (const int*)d_in[1];
    float*       out    = (float*)d_out;

    dim3 eg(HH / ETH, NB);            // (32, 8) = 256 blocks x 512 threads
    edge_pack_kernel<<<eg, 512>>>(target);

    loss_kernel<<<LOSS_BLOCKS, 256>>>(x, out);
}

// round 6
// speedup vs baseline: 1.7720x; 1.1216x over previous
#include <cuda_runtime.h>

#define NB   8
#define NC   6
#define HH   512
#define WW   512
#define HW   (HH * WW)           // 262144
#define NPIX (NB * HW)           // 2097152

#define ETH  16                  // edge strip height (full 512-wide rows)
#define SS   528                 // smem column stride; image col c stored at c+8

#define LOSS_BLOCKS ((NPIX / 4) / 256)   // 2048

#define L2E  1.4426950408889634f  // log2(e)
#define LN2  0.6931471805599453   // ln(2), applied once in finalize

// Global accumulators (log2-domain sums). Statically zero; loss kernel's
// last block resets them so every graph replay starts from zero.
__device__ double       g_A = 0.0;   // sum lp2 over all pixels
__device__ double       g_B = 0.0;   // sum S2  over edge pixels
__device__ double       g_C = 0.0;   // sum lp2 over edge pixels
__device__ unsigned int g_count = 0u;
__device__ unsigned int g_done  = 0u;
__device__ __align__(16) unsigned char g_pack[NPIX];  // label | (edge << 3)

__device__ __forceinline__ float ex2f(float v) {
    float r; asm("ex2.approx.f32 %0, %1;" : "=f"(r) : "f"(v)); return r;
}
__device__ __forceinline__ float lg2f(float v) {
    float r; asm("lg2.approx.f32 %0, %1;" : "=f"(r) : "f"(v)); return r;
}

// ---------------------------------------------------------------------------
// Kernel 1: full-width strip, exact integer 11x11 box sum, packed byte out.
// ---------------------------------------------------------------------------
__global__ void __launch_bounds__(512)
edge_pack_kernel(const int* __restrict__ target) {
    __shared__ unsigned char  t_s[(ETH + 10) * SS];   // 26*528 = 13728 B
    __shared__ unsigned short csum_s[ETH * SS];       // 16*528*2 = 16896 B

    const int tid = threadIdx.x;
    const int y0  = blockIdx.x * ETH;
    const int b   = blockIdx.y;
    const int* tb = target + b * HW;

    // Zero both arrays (guard columns / out-of-image rows must read as 0)
    {
        uint4* p1 = reinterpret_cast<uint4*>(t_s);      // 13728/16 = 858
        for (int i = tid; i < 858; i += 512) p1[i] = make_uint4(0, 0, 0, 0);
        uint4* p2 = reinterpret_cast<uint4*>(csum_s);   // 16896/16 = 1056
        for (int i = tid; i < 1056; i += 512) p2[i] = make_uint4(0, 0, 0, 0);
    }
    __syncthreads();

    // Phase 1: load rows y0-5 .. y0+20 (clamped) as bytes; col c at pos c+8
#pragma unroll
    for (int r = 0; r < ETH + 10; r++) {
        const int gy = y0 + r - 5;
        if (gy >= 0 && gy < HH)
            t_s[r * SS + tid + 8] = (unsigned char)tb[gy * WW + tid];
    }
    __syncthreads();

    // Phase 2: vertical sliding 11-sums; one column per thread
    {
        const int pos = tid + 8;
        int s = 0;
#pragma unroll
        for (int i = 0; i < 11; i++) s += t_s[i * SS + pos];
        csum_s[pos] = (unsigned short)s;
#pragma unroll
        for (int r = 1; r < ETH; r++) {
            s += (int)t_s[(r + 10) * SS + pos] - (int)t_s[(r - 1) * SS + pos];
            csum_s[r * SS + pos] = (unsigned short)s;
        }
    }
    __syncthreads();

    // Phase 3: 16 rows x 32 lanes; each thread 16 consecutive pixels.
    {
        const int r  = tid >> 5;          // 0..15
        const int xs = (tid & 31) * 16;   // 0,16,...,496

        unsigned int w[16];
        {
            const uint4* src = reinterpret_cast<const uint4*>(&csum_s[r * SS + xs]);
            uint4 u0 = src[0], u1 = src[1], u2 = src[2], u3 = src[3];
            w[0]=u0.x; w[1]=u0.y; w[2]=u0.z; w[3]=u0.w;
            w[4]=u1.x; w[5]=u1.y; w[6]=u1.z; w[7]=u1.w;
            w[8]=u2.x; w[9]=u2.y; w[10]=u2.z; w[11]=u2.w;
            w[12]=u3.x; w[13]=u3.y; w[14]=u3.z; w[15]=u3.w;
        }
#define CS(L) ((int)((w[(L) >> 1] >> (((L) & 1) * 16)) & 0xFFFFu))

        unsigned int lw[4];
        {
            const uint2* lp0 = reinterpret_cast<const uint2*>(
                &t_s[(r + 5) * SS + xs + 8]);
            uint2 l0 = lp0[0], l1 = lp0[1];
            lw[0] = l0.x; lw[1] = l0.y; lw[2] = l1.x; lw[3] = l1.y;
        }

        int s = 0;
#pragma unroll
        for (int d = 0; d < 11; d++) s += CS(3 + d);

        unsigned int out[4] = {0u, 0u, 0u, 0u};
#pragma unroll
        for (int k = 0; k < 16; k++) {
            if (k) s += CS(k + 13) - CS(k + 2);
            const int lab = (int)((lw[k >> 2] >> (8 * (k & 3))) & 0xFFu);
            const unsigned int e = (121 * lab != s) ? 1u : 0u;
            out[k >> 2] |= ((unsigned int)lab | (e << 3)) << (8 * (k & 3));
        }
#undef CS
        *reinterpret_cast<uint4*>(&g_pack[b * HW + (y0 + r) * WW + xs]) =
            make_uint4(out[0], out[1], out[2], out[3]);
    }
}

// ---------------------------------------------------------------------------
// Kernel 2: streaming fused log-softmax loss, 4 px/thread, NO register arrays
// (channel loop consumes each float4 immediately -> no local-memory spills).
// Works in log2 domain; ln2 applied once in the finalize.
// ---------------------------------------------------------------------------
__global__ void __launch_bounds__(256)
loss_kernel(const float* __restrict__ x, float* __restrict__ out) {
    const int t4 = blockIdx.x * blockDim.x + threadIdx.x;  // 0 .. NPIX/4-1
    const int p0 = t4 * 4;
    const int b  = p0 >> 18;         // / HW
    const int hw = p0 & (HW - 1);

    const float4* xb = reinterpret_cast<const float4*>(
        x + (size_t)b * NC * HW + hw);

    const unsigned int pk = *reinterpret_cast<const unsigned int*>(g_pack + p0);
    const int lab0 = (int)( pk        & 7u), e0 = (int)((pk >> 3)  & 1u);
    const int lab1 = (int)((pk >> 8)  & 7u), e1 = (int)((pk >> 11) & 1u);
    const int lab2 = (int)((pk >> 16) & 7u), e2 = (int)((pk >> 19) & 1u);
    const int lab3 = (int)((pk >> 24) & 7u), e3 = (int)((pk >> 27) & 1u);

    float es0 = 0.f, es1 = 0.f, es2 = 0.f, es3 = 0.f;   // sum 2^(x*log2e)
    float T0  = 0.f, T1  = 0.f, T2  = 0.f, T3  = 0.f;   // sum x
    float xl0 = 0.f, xl1 = 0.f, xl2 = 0.f, xl3 = 0.f;   // x at label

#pragma unroll
    for (int c = 0; c < NC; c++) {
        const float4 f = xb[c * (HW / 4)];
        es0 += ex2f(f.x * L2E);
        es1 += ex2f(f.y * L2E);
        es2 += ex2f(f.z * L2E);
        es3 += ex2f(f.w * L2E);
        T0 += f.x;  T1 += f.y;  T2 += f.z;  T3 += f.w;
        xl0 = (lab0 == c) ? f.x : xl0;
        xl1 = (lab1 == c) ? f.y : xl1;
        xl2 = (lab2 == c) ? f.z : xl2;
        xl3 = (lab3 == c) ? f.w : xl3;
    }

    // Per-pixel epilogue in log2 domain
    const float l0 = lg2f(es0), l1 = lg2f(es1), l2 = lg2f(es2), l3 = lg2f(es3);
    const float lp0 = fmaf(xl0, L2E, -l0);
    const float lp1 = fmaf(xl1, L2E, -l1);
    const float lp2 = fmaf(xl2, L2E, -l2);
    const float lp3 = fmaf(xl3, L2E, -l3);
    const float S0 = fmaf(l0, -6.0f, T0 * L2E);
    const float S1 = fmaf(l1, -6.0f, T1 * L2E);
    const float S2 = fmaf(l2, -6.0f, T2 * L2E);
    const float S3 = fmaf(l3, -6.0f, T3 * L2E);
    const float f0 = (float)e0, f1 = (float)e1, f2 = (float)e2, f3 = (float)e3;

    float accA = (lp0 + lp1) + (lp2 + lp3);
    float accB = fmaf(f0, S0,  fmaf(f1, S1,  fmaf(f2, S2,  f3 * S3)));
    float accC = fmaf(f0, lp0, fmaf(f1, lp1, fmaf(f2, lp2, f3 * lp3)));
    int   accN = (e0 + e1) + (e2 + e3);

    // Block reduction, then 4 global atomics
#pragma unroll
    for (int off = 16; off; off >>= 1) {
        accA += __shfl_down_sync(0xffffffffu, accA, off);
        accB += __shfl_down_sync(0xffffffffu, accB, off);
        accC += __shfl_down_sync(0xffffffffu, accC, off);
        accN += __shfl_down_sync(0xffffffffu, accN, off);
    }
    __shared__ float red[3 * 8];
    __shared__ int   redn[8];
    __shared__ bool  is_last;
    const int tid = threadIdx.x;
    const int lane = tid & 31, w = tid >> 5;
    if (lane == 0) { red[w] = accA; red[8 + w] = accB; red[16 + w] = accC; redn[w] = accN; }
    __syncthreads();
    if (tid < 8) {
        float a = red[tid], bb = red[8 + tid], c = red[16 + tid];
        int   n = redn[tid];
#pragma unroll
        for (int off = 4; off; off >>= 1) {
            a  += __shfl_down_sync(0x000000ffu, a, off);
            bb += __shfl_down_sync(0x000000ffu, bb, off);
            c  += __shfl_down_sync(0x000000ffu, c, off);
            n  += __shfl_down_sync(0x000000ffu, n, off);
        }
        if (tid == 0) {
            atomicAdd(&g_A, (double)a);
            atomicAdd(&g_B, (double)bb);
            atomicAdd(&g_C, (double)c);
            atomicAdd(&g_count, (unsigned int)n);
        }
    }

    // Last-block finalize: scalar math, output, reset
    if (tid == 0) {
        __threadfence();
        const unsigned int prev = atomicAdd(&g_done, 1u);
        is_last = (prev == (unsigned int)(LOSS_BLOCKS - 1));
    }
    __syncthreads();
    if (is_last && tid == 0) {
        const double A = atomicAdd(&g_A, 0.0);
        const double B = atomicAdd(&g_B, 0.0);
        const double C = atomicAdd(&g_C, 0.0);
        const unsigned int cnt = atomicAdd(&g_count, 0u);

        const double s  = fmin((double)cnt / (double)NPIX, 0.2);
        const double cl = 1.0 - 2.0 * s + s / 6.0;
        const double total = LN2 * (A + s * B + (cl - 1.0) * C);
        out[0] = (float)(-(total / (double)NPIX));

        g_A = 0.0; g_B = 0.0; g_C = 0.0;
        g_count = 0u; g_done = 0u;
    }
}

extern "C" void kernel_launch(void* const* d_in, const int* in_sizes, int n_in,
                              void* d_out, int out_size) {
    const float* x      = (const float*)d_in[0];
    const int*   target = (const int*)d_in[1];
    float*       out    = (float*)d_out;

    dim3 eg(HH / ETH, NB);            // (32, 8) = 256 blocks x 512 threads
    edge_pack_kernel<<<eg, 512>>>(target);

    loss_kernel<<<LOSS_BLOCKS, 256>>>(x, out);
}